// round 16
// baseline (speedup 1.0000x reference)
#include <cuda_runtime.h>
#include <cstdint>

#define BB 1024
#define TT 2048
#define FF 16
#define SS 300    // FORWARD_STEPS
#define BPB 7     // batch elements per block
#define GRID 147  // ceil(1024/7); occ 1 -> all blocks co-resident
#define NT 384    // 12 warps; >= SS so one thread per step
#define ITERS 11  // ceil(BPB*SS*2 / NT) = ceil(4200/384)
#define MROW 160  // bytes per step-row of g_mask (147 used + pad, 16B-aligned)

// Per-(step, block) 4-bit validity masks, written by PLAIN stores (full
// overwrite every launch -> no memset needed, no atomics). Pad bytes
// [147..159] are never written and stay 0 from static zero-init.
__device__ unsigned char g_mask[SS][MROW];

// Self-resetting barrier counter: 0 -> GRID (arrivals) -> 2*GRID (exits),
// and the last exiter resets it to 0, provably after every block passed the
// spin. Returns to initial state each launch -> graph-replay deterministic.
__device__ unsigned g_cnt;

// ---------------------------------------------------------------------------
// SINGLE graph node: 147 blocks x 384 threads, 1 CTA/SM, no memset node.
// Block k owns batches [k*7, k*7+nb). Thread t (< 300) owns step t.
//
// Phase 1: chunk-coalesced, front-batched staging (thread i loads the i-th
//   16B chunk of the block's rows; all ~11 LDG.128s in flight).
// Phase 2: y_j once per (b,j), reference's exact _rn op order, overlapped.
// Phase 3: drain to smem; sync; register-resident gather; plain-store the
//   block's mask byte per step; self-resetting 147-arrival barrier; OR the
//   147 mask bytes (10 x __ldcg uint4, byte-fold); select; emit.
//
// Bit-exactness: identical _rn op sequences; y_j >= 0 -> SS-1 clamp == TT-1
// clamp (rel_err 0.0 on every passing round since R2).
// ---------------------------------------------------------------------------
__global__ void __launch_bounds__(NT, 1)
k_all(const float* __restrict__ x, const float* __restrict__ wp,
      float* __restrict__ out) {
    const int tid = threadIdx.x;
    const int bid = blockIdx.x;
    const int b0  = bid * BPB;
    const int nb  = min(BPB, BB - b0);
    const int nchunk = nb * SS * 2;

    __shared__ float s_feat[BPB][SS][5];  // features 10..13 (+pad; 5 coprime 32 banks)
    __shared__ float s_y[BPB][4];

    // ---- phase 1: front-batch ALL chunk loads into registers ----
    float4 ch[ITERS];
#pragma unroll
    for (int k = 0; k < ITERS; k++) {
        int i = tid + k * NT;
        if (i < nchunk) {
            int rg   = i >> 1;            // row index within block (0..nb*300-1)
            int half = i & 1;             // 0: f8..f11, 1: f12..f15
            int bl = rg / SS, r = rg - bl * SS;
            const float* base = x + (size_t)(b0 + bl) * (TT * FF) + r * FF;
            ch[k] = *reinterpret_cast<const float4*>(base + 8 + half * 4);
        }
    }

    // ---- phase 2: y_j once per (b,j), overlapped with in-flight loads ----
    if (tid < nb * 4) {
        int bl = tid >> 2;
        int j  = (tid & 3) + 1;
        const float* xl = x + (size_t)(b0 + bl) * (TT * FF) + (size_t)(TT - 1) * FF;
        float w = *wp;
        float d = xl[0];
        for (int k = 1; k < j; k++) d = __fadd_rn(d, xl[k]);  // sequential prefix sum
        float den = __fadd_rn(w, __fmul_rn(xl[4 + j], 25.0f));
        float td  = __fdiv_rn(__fmul_rn(d, 150.0f), den);
        s_y[bl][j - 1] = __fmul_rn(td, 10.0f);
    }

    // ---- phase 3: drain registers into smem (2 useful floats per chunk) ----
#pragma unroll
    for (int k = 0; k < ITERS; k++) {
        int i = tid + k * NT;
        if (i < nchunk) {
            int rg   = i >> 1;
            int half = i & 1;
            int bl = rg / SS, r = rg - bl * SS;
            if (half == 0) {
                s_feat[bl][r][0] = ch[k].z;   // f10
                s_feat[bl][r][1] = ch[k].w;   // f11
            } else {
                s_feat[bl][r][2] = ch[k].x;   // f12
                s_feat[bl][r][3] = ch[k].y;   // f13
            }
        }
    }
    __syncthreads();

    // ---- gather into registers; per-block mask byte per step ----
    const int  s    = tid;            // one step per thread; NT >= SS covers all
    const bool owns = (s < SS);

    float4   vals[BPB];
    unsigned msk = 0u;

    if (owns) {
        float sf = (float)s;
#pragma unroll
        for (int bl = 0; bl < BPB; bl++) {
            if (bl >= nb) break;
            int r0 = min(max((int)__fsub_rn(sf, s_y[bl][0]), 0), SS - 1);
            int r1 = min(max((int)__fsub_rn(sf, s_y[bl][1]), 0), SS - 1);
            int r2 = min(max((int)__fsub_rn(sf, s_y[bl][2]), 0), SS - 1);
            int r3 = min(max((int)__fsub_rn(sf, s_y[bl][3]), 0), SS - 1);
            float4 o;
            o.x = s_feat[bl][r0][0];
            o.y = s_feat[bl][r1][1];
            o.z = s_feat[bl][r2][2];
            o.w = s_feat[bl][r3][3];
            vals[bl] = o;
            msk |= (o.x != 0.0f ? 1u : 0u) | (o.y != 0.0f ? 2u : 0u) |
                   (o.z != 0.0f ? 4u : 0u) | (o.w != 0.0f ? 8u : 0u);
        }
        g_mask[s][bid] = (unsigned char)msk;   // plain store, unconditional
    }

    // ---- self-resetting grid barrier (147 co-resident blocks) ----
    __threadfence();
    __syncthreads();
    if (tid == 0) {
        atomicAdd(&g_cnt, 1u);                        // arrival: 0 -> GRID
        volatile unsigned* cv = &g_cnt;
        while (*cv < (unsigned)GRID) { __nanosleep(32); }
        unsigned d = atomicAdd(&g_cnt, 1u);           // exit:  GRID -> 2*GRID
        if (d == 2u * GRID - 1u) *cv = 0u;            // last exiter resets
        __threadfence();
    }
    __syncthreads();

    // ---- reduce the 147 mask bytes for this step, select, emit ----
    if (owns) {
        const uint4* __restrict__ row = reinterpret_cast<const uint4*>(g_mask[s]);
        uint4 m4[MROW / 16];
#pragma unroll
        for (int k = 0; k < MROW / 16; k++) m4[k] = __ldcg(&row[k]);  // front-batched
        unsigned wv = 0u;
#pragma unroll
        for (int k = 0; k < MROW / 16; k++)
            wv |= m4[k].x | m4[k].y | m4[k].z | m4[k].w;
        wv |= wv >> 16;
        wv |= wv >> 8;
        unsigned mm = wv & 0xFu;                 // OR of all blocks' 4-bit masks
        int sel = mm ? (__ffs(mm) - 1) : -1;

#pragma unroll
        for (int bl = 0; bl < BPB; bl++) {
            if (bl >= nb) break;
            float4 o = vals[bl];
            float r = 0.0f;
            r = (sel == 0) ? o.x : r;
            r = (sel == 1) ? o.y : r;
            r = (sel == 2) ? o.z : r;
            r = (sel == 3) ? o.w : r;
            out[(size_t)(b0 + bl) * SS + s] = r;
        }
    }
}

extern "C" void kernel_launch(void* const* d_in, const int* in_sizes, int n_in,
                              void* d_out, int out_size) {
    // metadata order: vi(0), delta_y(1), v_previous(2), x_input(3), w(4)
    const float* x = (const float*)d_in[3];
    const float* w = (const float*)d_in[4];
    float* out = (float*)d_out;

    k_all<<<GRID, NT>>>(x, w, out);   // single graph node
}

// round 17
// speedup vs baseline: 1.4650x; 1.4650x over previous
#include <cuda_runtime.h>
#include <cstdint>

#define BB 1024
#define TT 2048
#define FF 16
#define SS 300    // FORWARD_STEPS
#define BPB 7     // batch elements per block
#define GRID 147  // ceil(1024/7); occ 1 -> all blocks co-resident
#define NT 320    // R14's proven config (384 spilled: R16 regs 115->80, +3us)
#define ITERS 14  // ceil(BPB*SS*2 / NT) = ceil(4200/320)
#define MROW 160  // bytes per step-row of g_mask (147 used + 13 pad, 16B-aligned)

// Per-(step, block) 4-bit validity masks, written by PLAIN stores (full
// overwrite every launch -> no memset node, no atomics). Pad bytes
// [147..159] are never written and stay 0 from static zero-init.
__device__ unsigned char g_mask[SS][MROW];

// Self-resetting barrier counter: 0 -> GRID (arrivals) -> 2*GRID (exits);
// the 2*GRID-th adder resets to 0, provably after every block passed the
// spin. Returns to initial state each launch -> graph-replay deterministic.
__device__ unsigned g_cnt;

// ---------------------------------------------------------------------------
// SINGLE graph node: 147 blocks x 320 threads, 1 CTA/SM (R14 base config;
// only the mask/barrier protocol differs -> no memset node).
// Block k owns batches [k*7, k*7+nb). Thread t (< 300) owns step t.
//
// Phase 1: chunk-coalesced, front-batched staging (thread i loads the i-th
//   16B chunk; warp touches 8 lines per LDG.128; all 14 loads in flight).
// Phase 2: y_j once per (b,j), reference's exact _rn op order, overlapped.
// Phase 3: drain to smem; sync; register-resident gather; plain-store this
//   block's mask byte per step; self-resetting 147-arrival barrier; OR the
//   147 mask bytes (10 front-batched __ldcg uint4, byte-fold); select; emit.
//
// Bit-exactness: identical _rn op sequences; y_j >= 0 -> SS-1 clamp == TT-1
// clamp (rel_err 0.0 on every passing round since R2).
// ---------------------------------------------------------------------------
__global__ void __launch_bounds__(NT, 1)
k_all(const float* __restrict__ x, const float* __restrict__ wp,
      float* __restrict__ out) {
    const int tid = threadIdx.x;
    const int bid = blockIdx.x;
    const int b0  = bid * BPB;
    const int nb  = min(BPB, BB - b0);
    const int nchunk = nb * SS * 2;

    __shared__ float s_feat[BPB][SS][5];  // features 10..13 (+pad; 5 coprime 32 banks)
    __shared__ float s_y[BPB][4];

    // ---- phase 1: front-batch ALL chunk loads into registers ----
    float4 ch[ITERS];
#pragma unroll
    for (int k = 0; k < ITERS; k++) {
        int i = tid + k * NT;
        if (i < nchunk) {
            int rg   = i >> 1;            // row index within block (0..nb*300-1)
            int half = i & 1;             // 0: f8..f11, 1: f12..f15
            int bl = rg / SS, r = rg - bl * SS;
            const float* base = x + (size_t)(b0 + bl) * (TT * FF) + r * FF;
            ch[k] = *reinterpret_cast<const float4*>(base + 8 + half * 4);
        }
    }

    // ---- phase 2: y_j once per (b,j), overlapped with in-flight loads ----
    if (tid < nb * 4) {
        int bl = tid >> 2;
        int j  = (tid & 3) + 1;
        const float* xl = x + (size_t)(b0 + bl) * (TT * FF) + (size_t)(TT - 1) * FF;
        float w = *wp;
        float d = xl[0];
        for (int k = 1; k < j; k++) d = __fadd_rn(d, xl[k]);  // sequential prefix sum
        float den = __fadd_rn(w, __fmul_rn(xl[4 + j], 25.0f));
        float td  = __fdiv_rn(__fmul_rn(d, 150.0f), den);
        s_y[bl][j - 1] = __fmul_rn(td, 10.0f);
    }

    // ---- phase 3: drain registers into smem (2 useful floats per chunk) ----
#pragma unroll
    for (int k = 0; k < ITERS; k++) {
        int i = tid + k * NT;
        if (i < nchunk) {
            int rg   = i >> 1;
            int half = i & 1;
            int bl = rg / SS, r = rg - bl * SS;
            if (half == 0) {
                s_feat[bl][r][0] = ch[k].z;   // f10
                s_feat[bl][r][1] = ch[k].w;   // f11
            } else {
                s_feat[bl][r][2] = ch[k].x;   // f12
                s_feat[bl][r][3] = ch[k].y;   // f13
            }
        }
    }
    __syncthreads();

    // ---- gather into registers; plain-store this block's mask byte ----
    const int  s    = tid;            // one step per thread; NT >= SS covers all
    const bool owns = (s < SS);

    float4   vals[BPB];
    unsigned msk = 0u;

    if (owns) {
        float sf = (float)s;
#pragma unroll
        for (int bl = 0; bl < BPB; bl++) {
            if (bl >= nb) break;
            int r0 = min(max((int)__fsub_rn(sf, s_y[bl][0]), 0), SS - 1);
            int r1 = min(max((int)__fsub_rn(sf, s_y[bl][1]), 0), SS - 1);
            int r2 = min(max((int)__fsub_rn(sf, s_y[bl][2]), 0), SS - 1);
            int r3 = min(max((int)__fsub_rn(sf, s_y[bl][3]), 0), SS - 1);
            float4 o;
            o.x = s_feat[bl][r0][0];
            o.y = s_feat[bl][r1][1];
            o.z = s_feat[bl][r2][2];
            o.w = s_feat[bl][r3][3];
            vals[bl] = o;
            msk |= (o.x != 0.0f ? 1u : 0u) | (o.y != 0.0f ? 2u : 0u) |
                   (o.z != 0.0f ? 4u : 0u) | (o.w != 0.0f ? 8u : 0u);
        }
        g_mask[s][bid] = (unsigned char)msk;   // plain store, unconditional
    }

    // ---- self-resetting grid barrier (147 co-resident blocks) ----
    __threadfence();
    __syncthreads();
    if (tid == 0) {
        atomicAdd(&g_cnt, 1u);                        // arrival: 0 -> GRID
        volatile unsigned* cv = &g_cnt;
        while (*cv < (unsigned)GRID) { __nanosleep(32); }
        unsigned d = atomicAdd(&g_cnt, 1u);           // exit:  GRID -> 2*GRID
        if (d == 2u * GRID - 1u) *cv = 0u;            // last exiter resets
        __threadfence();
    }
    __syncthreads();

    // ---- reduce the 147 mask bytes for this step, select, emit ----
    if (owns) {
        const uint4* __restrict__ row = reinterpret_cast<const uint4*>(g_mask[s]);
        uint4 m4[MROW / 16];
#pragma unroll
        for (int k = 0; k < MROW / 16; k++) m4[k] = __ldcg(&row[k]);  // front-batched, MLP=10
        unsigned wv = 0u;
#pragma unroll
        for (int k = 0; k < MROW / 16; k++)
            wv |= m4[k].x | m4[k].y | m4[k].z | m4[k].w;
        wv |= wv >> 16;
        wv |= wv >> 8;
        unsigned mm = wv & 0xFu;                 // OR of all blocks' 4-bit masks
        int sel = mm ? (__ffs(mm) - 1) : -1;

#pragma unroll
        for (int bl = 0; bl < BPB; bl++) {
            if (bl >= nb) break;
            float4 o = vals[bl];
            float r = 0.0f;
            r = (sel == 0) ? o.x : r;
            r = (sel == 1) ? o.y : r;
            r = (sel == 2) ? o.z : r;
            r = (sel == 3) ? o.w : r;
            out[(size_t)(b0 + bl) * SS + s] = r;
        }
    }
}

extern "C" void kernel_launch(void* const* d_in, const int* in_sizes, int n_in,
                              void* d_out, int out_size) {
    // metadata order: vi(0), delta_y(1), v_previous(2), x_input(3), w(4)
    const float* x = (const float*)d_in[3];
    const float* w = (const float*)d_in[4];
    float* out = (float*)d_out;

    k_all<<<GRID, NT>>>(x, w, out);   // single graph node, no memset
}